// round 1
// baseline (speedup 1.0000x reference)
#include <cuda_runtime.h>

// GTConv: out[c,r,e] = softmax(weight, axis=1)[c,r] * edge_w[r,e]
// Shapes: edge_w [R=8, E], weight [C=4, R=8].
// Output buffer layout assumed: out (C*R*E floats) followed by Filter (C*R floats).

#define GT_R 8
#define GT_C 4

// ---------------------------------------------------------------------------
// Main vectorized kernel: grid.y = r, grid.x tiles E/4 (float4 elements).
// Each thread: 1 float4 load, 4 float4 stores (one per out-channel).
// Softmax of the 4x8 weight matrix is recomputed per block in smem (cheap:
// 4 threads x 8 exps per block; negligible vs 320MB of HBM traffic).
// ---------------------------------------------------------------------------
__global__ void gtconv_vec4_kernel(const float4* __restrict__ ew,
                                   const float*  __restrict__ weight,
                                   float4* __restrict__ out,
                                   int e4)   // E/4
{
    __shared__ float F[GT_C][GT_R];
    const int tid = threadIdx.x;
    if (tid < GT_C) {
        float w[GT_R];
        float m = -3.402823e38f;
#pragma unroll
        for (int r = 0; r < GT_R; ++r) { w[r] = weight[tid * GT_R + r]; m = fmaxf(m, w[r]); }
        float s = 0.f;
#pragma unroll
        for (int r = 0; r < GT_R; ++r) { w[r] = __expf(w[r] - m); s += w[r]; }
        const float inv = 1.0f / s;
#pragma unroll
        for (int r = 0; r < GT_R; ++r) F[tid][r] = w[r] * inv;
    }
    __syncthreads();

    const int r  = blockIdx.y;
    const long long e = (long long)blockIdx.x * blockDim.x + tid;
    if (e >= e4) return;

    const long long re_total = (long long)GT_R * e4;  // total float4s per channel
    const long long idx = (long long)r * e4 + e;

    const float4 v = ew[idx];
#pragma unroll
    for (int c = 0; c < GT_C; ++c) {
        const float f = F[c][r];
        float4 o;
        o.x = v.x * f; o.y = v.y * f; o.z = v.z * f; o.w = v.w * f;
        out[(long long)c * re_total + idx] = o;
    }
}

// Scalar fallback if E is not divisible by 4.
__global__ void gtconv_scalar_kernel(const float* __restrict__ ew,
                                     const float* __restrict__ weight,
                                     float* __restrict__ out,
                                     long long E)
{
    __shared__ float F[GT_C][GT_R];
    const int tid = threadIdx.x;
    if (tid < GT_C) {
        float w[GT_R];
        float m = -3.402823e38f;
#pragma unroll
        for (int r = 0; r < GT_R; ++r) { w[r] = weight[tid * GT_R + r]; m = fmaxf(m, w[r]); }
        float s = 0.f;
#pragma unroll
        for (int r = 0; r < GT_R; ++r) { w[r] = __expf(w[r] - m); s += w[r]; }
        const float inv = 1.0f / s;
#pragma unroll
        for (int r = 0; r < GT_R; ++r) F[tid][r] = w[r] * inv;
    }
    __syncthreads();

    const int r = blockIdx.y;
    const long long e = (long long)blockIdx.x * blockDim.x + tid;
    if (e >= E) return;

    const long long re_total = (long long)GT_R * E;
    const long long idx = (long long)r * E + e;
    const float v = ew[idx];
#pragma unroll
    for (int c = 0; c < GT_C; ++c)
        out[(long long)c * re_total + idx] = v * F[c][r];
}

// Tiny kernel: write the Filter [C, R] tail of the output buffer.
__global__ void gtconv_filter_kernel(const float* __restrict__ weight,
                                     float* __restrict__ out_tail)
{
    const int c = threadIdx.x;   // 0..3
    if (c >= GT_C) return;
    float w[GT_R];
    float m = -3.402823e38f;
#pragma unroll
    for (int r = 0; r < GT_R; ++r) { w[r] = weight[c * GT_R + r]; m = fmaxf(m, w[r]); }
    float s = 0.f;
#pragma unroll
    for (int r = 0; r < GT_R; ++r) { w[r] = __expf(w[r] - m); s += w[r]; }
    const float inv = 1.0f / s;
#pragma unroll
    for (int r = 0; r < GT_R; ++r) out_tail[c * GT_R + r] = w[r] * inv;
}

extern "C" void kernel_launch(void* const* d_in, const int* in_sizes, int n_in,
                              void* d_out, int out_size)
{
    // Identify inputs: edge_w is the big array (R*E), weight is C*R = 32.
    const float* edge_w = (const float*)d_in[0];
    const float* weight = (const float*)d_in[1];
    long long n_ew = in_sizes[0];
    if (n_in >= 2 && in_sizes[1] > in_sizes[0]) {
        edge_w = (const float*)d_in[1];
        weight = (const float*)d_in[0];
        n_ew = in_sizes[1];
    }

    const long long E = n_ew / GT_R;
    float* out = (float*)d_out;

    const int threads = 256;
    if ((E & 3LL) == 0) {
        const int e4 = (int)(E / 4);
        dim3 grid((unsigned)((e4 + threads - 1) / threads), GT_R, 1);
        gtconv_vec4_kernel<<<grid, threads>>>(
            (const float4*)edge_w, weight, (float4*)out, e4);
    } else {
        dim3 grid((unsigned)((E + threads - 1) / threads), GT_R, 1);
        gtconv_scalar_kernel<<<grid, threads>>>(edge_w, weight, out, E);
    }

    // Filter tail, if the output buffer includes it.
    const long long main_elems = (long long)GT_C * GT_R * E;
    if ((long long)out_size >= main_elems + GT_C * GT_R) {
        gtconv_filter_kernel<<<1, 32>>>(weight, out + main_elems);
    }
}

// round 2
// speedup vs baseline: 1.0415x; 1.0415x over previous
#include <cuda_runtime.h>

// GTConv: out[c,r,e] = softmax(weight, axis=1)[c,r] * edge_w[r,e]
// Shapes: edge_w [R=8, E], weight [C=4, R=8].
// Output layout: out (C*R*E floats) followed by Filter (C*R floats).

#define GT_R 8
#define GT_C 4

// ---------------------------------------------------------------------------
// Fused vectorized kernel: grid.y = r, grid.x tiles E/4 (float4 elements).
// Each thread: 1 float4 streaming load, 4 float4 streaming stores.
// Block (0,0) also writes the Filter [C,R] tail (fused, no extra launch).
// ---------------------------------------------------------------------------
__global__ void gtconv_vec4_fused_kernel(const float4* __restrict__ ew,
                                         const float*  __restrict__ weight,
                                         float4* __restrict__ out,
                                         float*  __restrict__ out_tail, // may be null
                                         int e4)   // E/4
{
    __shared__ float F[GT_C][GT_R];
    const int tid = threadIdx.x;
    if (tid < GT_C) {
        float w[GT_R];
        float m = -3.402823e38f;
#pragma unroll
        for (int r = 0; r < GT_R; ++r) { w[r] = weight[tid * GT_R + r]; m = fmaxf(m, w[r]); }
        float s = 0.f;
#pragma unroll
        for (int r = 0; r < GT_R; ++r) { w[r] = __expf(w[r] - m); s += w[r]; }
        const float inv = 1.0f / s;
#pragma unroll
        for (int r = 0; r < GT_R; ++r) F[tid][r] = w[r] * inv;
        // Fused Filter tail write from one block only.
        if (out_tail != nullptr && blockIdx.x == 0 && blockIdx.y == 0) {
#pragma unroll
            for (int r = 0; r < GT_R; ++r) out_tail[tid * GT_R + r] = w[r] * inv;
        }
    }
    __syncthreads();

    const int r  = blockIdx.y;
    const long long e = (long long)blockIdx.x * blockDim.x + tid;
    if (e >= e4) return;

    const long long re_total = (long long)GT_R * e4;  // float4s per channel
    const long long idx = (long long)r * e4 + e;

    const float4 v = __ldcs(&ew[idx]);   // read-once: evict-first
    const float f0 = F[0][r], f1 = F[1][r], f2 = F[2][r], f3 = F[3][r];

    float4 o;
    o.x = v.x * f0; o.y = v.y * f0; o.z = v.z * f0; o.w = v.w * f0;
    __stcs(&out[0 * re_total + idx], o);
    o.x = v.x * f1; o.y = v.y * f1; o.z = v.z * f1; o.w = v.w * f1;
    __stcs(&out[1 * re_total + idx], o);
    o.x = v.x * f2; o.y = v.y * f2; o.z = v.z * f2; o.w = v.w * f2;
    __stcs(&out[2 * re_total + idx], o);
    o.x = v.x * f3; o.y = v.y * f3; o.z = v.z * f3; o.w = v.w * f3;
    __stcs(&out[3 * re_total + idx], o);
}

// Scalar fallback if E is not divisible by 4 (also fused tail).
__global__ void gtconv_scalar_kernel(const float* __restrict__ ew,
                                     const float* __restrict__ weight,
                                     float* __restrict__ out,
                                     float* __restrict__ out_tail,
                                     long long E)
{
    __shared__ float F[GT_C][GT_R];
    const int tid = threadIdx.x;
    if (tid < GT_C) {
        float w[GT_R];
        float m = -3.402823e38f;
#pragma unroll
        for (int r = 0; r < GT_R; ++r) { w[r] = weight[tid * GT_R + r]; m = fmaxf(m, w[r]); }
        float s = 0.f;
#pragma unroll
        for (int r = 0; r < GT_R; ++r) { w[r] = __expf(w[r] - m); s += w[r]; }
        const float inv = 1.0f / s;
#pragma unroll
        for (int r = 0; r < GT_R; ++r) F[tid][r] = w[r] * inv;
        if (out_tail != nullptr && blockIdx.x == 0 && blockIdx.y == 0) {
#pragma unroll
            for (int r = 0; r < GT_R; ++r) out_tail[tid * GT_R + r] = w[r] * inv;
        }
    }
    __syncthreads();

    const int r = blockIdx.y;
    const long long e = (long long)blockIdx.x * blockDim.x + tid;
    if (e >= E) return;

    const long long re_total = (long long)GT_R * E;
    const long long idx = (long long)r * E + e;
    const float v = __ldcs(&ew[idx]);
#pragma unroll
    for (int c = 0; c < GT_C; ++c)
        __stcs(&out[(long long)c * re_total + idx], v * F[c][r]);
}

extern "C" void kernel_launch(void* const* d_in, const int* in_sizes, int n_in,
                              void* d_out, int out_size)
{
    // Identify inputs: edge_w is the big array (R*E), weight is C*R = 32.
    const float* edge_w = (const float*)d_in[0];
    const float* weight = (const float*)d_in[1];
    long long n_ew = in_sizes[0];
    if (n_in >= 2 && in_sizes[1] > in_sizes[0]) {
        edge_w = (const float*)d_in[1];
        weight = (const float*)d_in[0];
        n_ew = in_sizes[1];
    }

    const long long E = n_ew / GT_R;
    float* out = (float*)d_out;

    const long long main_elems = (long long)GT_C * GT_R * E;
    float* out_tail =
        ((long long)out_size >= main_elems + GT_C * GT_R) ? (out + main_elems) : nullptr;

    const int threads = 256;
    if ((E & 3LL) == 0) {
        const int e4 = (int)(E / 4);
        dim3 grid((unsigned)((e4 + threads - 1) / threads), GT_R, 1);
        gtconv_vec4_fused_kernel<<<grid, threads>>>(
            (const float4*)edge_w, weight, (float4*)out, out_tail, e4);
    } else {
        dim3 grid((unsigned)((E + threads - 1) / threads), GT_R, 1);
        gtconv_scalar_kernel<<<grid, threads>>>(edge_w, weight, out, out_tail, E);
    }
}

// round 3
// speedup vs baseline: 1.0705x; 1.0278x over previous
#include <cuda_runtime.h>

// GTConv: out[c,r,e] = softmax(weight, axis=1)[c,r] * edge_w[r,e]
// Shapes: edge_w [R=8, E], weight [C=4, R=8].
// Output layout: out (C*R*E floats) followed by Filter (C*R floats).

#define GT_R 8
#define GT_C 4
#define VPT 2   // float4s per thread

// ---------------------------------------------------------------------------
// Fused vectorized kernel: grid.y = r, grid.x tiles e4 in chunks of
// blockDim.x * VPT float4s. Each thread: VPT streaming float4 loads issued
// up-front (MLP), then 4*VPT streaming float4 stores.
// Block (0,0) also writes the Filter [C,R] tail (fused, no extra launch).
// ---------------------------------------------------------------------------
__global__ void gtconv_vec4x2_kernel(const float4* __restrict__ ew,
                                     const float*  __restrict__ weight,
                                     float4* __restrict__ out,
                                     float*  __restrict__ out_tail, // may be null
                                     int e4)   // E/4
{
    __shared__ float F[GT_C][GT_R];
    const int tid = threadIdx.x;
    if (tid < GT_C) {
        float w[GT_R];
        float m = -3.402823e38f;
#pragma unroll
        for (int r = 0; r < GT_R; ++r) { w[r] = weight[tid * GT_R + r]; m = fmaxf(m, w[r]); }
        float s = 0.f;
#pragma unroll
        for (int r = 0; r < GT_R; ++r) { w[r] = __expf(w[r] - m); s += w[r]; }
        const float inv = 1.0f / s;
#pragma unroll
        for (int r = 0; r < GT_R; ++r) F[tid][r] = w[r] * inv;
        if (out_tail != nullptr && blockIdx.x == 0 && blockIdx.y == 0) {
#pragma unroll
            for (int r = 0; r < GT_R; ++r) out_tail[tid * GT_R + r] = w[r] * inv;
        }
    }
    __syncthreads();

    const int r = blockIdx.y;
    const int bd = blockDim.x;
    const long long base = (long long)blockIdx.x * (bd * VPT) + tid;
    const long long re_total = (long long)GT_R * e4;   // float4s per channel
    const long long rbase = (long long)r * e4;

    const float f0 = F[0][r], f1 = F[1][r], f2 = F[2][r], f3 = F[3][r];

    if (base + (VPT - 1) * (long long)bd < e4) {
        // Fast path: all VPT elements valid. Batch the loads first (MLP).
        float4 v[VPT];
        long long idx[VPT];
#pragma unroll
        for (int i = 0; i < VPT; ++i) {
            idx[i] = rbase + base + (long long)i * bd;
            v[i] = __ldcs(&ew[idx[i]]);
        }
#pragma unroll
        for (int i = 0; i < VPT; ++i) {
            float4 o;
            o.x = v[i].x * f0; o.y = v[i].y * f0; o.z = v[i].z * f0; o.w = v[i].w * f0;
            __stcs(&out[0 * re_total + idx[i]], o);
            o.x = v[i].x * f1; o.y = v[i].y * f1; o.z = v[i].z * f1; o.w = v[i].w * f1;
            __stcs(&out[1 * re_total + idx[i]], o);
            o.x = v[i].x * f2; o.y = v[i].y * f2; o.z = v[i].z * f2; o.w = v[i].w * f2;
            __stcs(&out[2 * re_total + idx[i]], o);
            o.x = v[i].x * f3; o.y = v[i].y * f3; o.z = v[i].z * f3; o.w = v[i].w * f3;
            __stcs(&out[3 * re_total + idx[i]], o);
        }
    } else {
        // Tail path: per-element guard.
#pragma unroll
        for (int i = 0; i < VPT; ++i) {
            const long long e = base + (long long)i * bd;
            if (e >= e4) break;
            const long long idx = rbase + e;
            const float4 v = __ldcs(&ew[idx]);
            float4 o;
            o.x = v.x * f0; o.y = v.y * f0; o.z = v.z * f0; o.w = v.w * f0;
            __stcs(&out[0 * re_total + idx], o);
            o.x = v.x * f1; o.y = v.y * f1; o.z = v.z * f1; o.w = v.w * f1;
            __stcs(&out[1 * re_total + idx], o);
            o.x = v.x * f2; o.y = v.y * f2; o.z = v.z * f2; o.w = v.w * f2;
            __stcs(&out[2 * re_total + idx], o);
            o.x = v.x * f3; o.y = v.y * f3; o.z = v.z * f3; o.w = v.w * f3;
            __stcs(&out[3 * re_total + idx], o);
        }
    }
}

// Scalar fallback if E is not divisible by 4 (also fused tail).
__global__ void gtconv_scalar_kernel(const float* __restrict__ ew,
                                     const float* __restrict__ weight,
                                     float* __restrict__ out,
                                     float* __restrict__ out_tail,
                                     long long E)
{
    __shared__ float F[GT_C][GT_R];
    const int tid = threadIdx.x;
    if (tid < GT_C) {
        float w[GT_R];
        float m = -3.402823e38f;
#pragma unroll
        for (int r = 0; r < GT_R; ++r) { w[r] = weight[tid * GT_R + r]; m = fmaxf(m, w[r]); }
        float s = 0.f;
#pragma unroll
        for (int r = 0; r < GT_R; ++r) { w[r] = __expf(w[r] - m); s += w[r]; }
        const float inv = 1.0f / s;
#pragma unroll
        for (int r = 0; r < GT_R; ++r) F[tid][r] = w[r] * inv;
        if (out_tail != nullptr && blockIdx.x == 0 && blockIdx.y == 0) {
#pragma unroll
            for (int r = 0; r < GT_R; ++r) out_tail[tid * GT_R + r] = w[r] * inv;
        }
    }
    __syncthreads();

    const int r = blockIdx.y;
    const long long e = (long long)blockIdx.x * blockDim.x + tid;
    if (e >= E) return;

    const long long re_total = (long long)GT_R * E;
    const long long idx = (long long)r * E + e;
    const float v = __ldcs(&ew[idx]);
#pragma unroll
    for (int c = 0; c < GT_C; ++c)
        __stcs(&out[(long long)c * re_total + idx], v * F[c][r]);
}

extern "C" void kernel_launch(void* const* d_in, const int* in_sizes, int n_in,
                              void* d_out, int out_size)
{
    // Identify inputs: edge_w is the big array (R*E), weight is C*R = 32.
    const float* edge_w = (const float*)d_in[0];
    const float* weight = (const float*)d_in[1];
    long long n_ew = in_sizes[0];
    if (n_in >= 2 && in_sizes[1] > in_sizes[0]) {
        edge_w = (const float*)d_in[1];
        weight = (const float*)d_in[0];
        n_ew = in_sizes[1];
    }

    const long long E = n_ew / GT_R;
    float* out = (float*)d_out;

    const long long main_elems = (long long)GT_C * GT_R * E;
    float* out_tail =
        ((long long)out_size >= main_elems + GT_C * GT_R) ? (out + main_elems) : nullptr;

    const int threads = 256;
    if ((E & 3LL) == 0) {
        const int e4 = (int)(E / 4);
        const int per_block = threads * VPT;
        dim3 grid((unsigned)((e4 + per_block - 1) / per_block), GT_R, 1);
        gtconv_vec4x2_kernel<<<grid, threads>>>(
            (const float4*)edge_w, weight, (float4*)out, out_tail, e4);
    } else {
        dim3 grid((unsigned)((E + threads - 1) / threads), GT_R, 1);
        gtconv_scalar_kernel<<<grid, threads>>>(edge_w, weight, out, out_tail, E);
    }
}